// round 5
// baseline (speedup 1.0000x reference)
#include <cuda_runtime.h>
#include <math.h>

#define TPB     256
#define ROWSB   64
#define HID     192
#define G4      768
#define TSTEPS  20
#define NBATCH  131072
#define PSTR    388   // packed w row stride in floats (2-way max bank grouping)

#define W_S_FLOATS (96 * PSTR)
#define H_S_FLOATS (ROWSB * HID)
#define SMEM_FLOATS (W_S_FLOATS + H_S_FLOATS + ROWSB*2 + G4*2 + G4 + 2*HID + 2)
#define SMEM_BYTES  (SMEM_FLOATS * 4)

// ---- f32x2 packed helpers (FFMA2 only reachable via PTX on sm_103a) ----
__device__ __forceinline__ unsigned long long pack2(float lo, float hi) {
    unsigned long long r;
    asm("mov.b64 %0, {%1, %2};" : "=l"(r) : "f"(lo), "f"(hi));
    return r;
}
__device__ __forceinline__ unsigned long long splat2(float x) {
    unsigned long long r;
    asm("mov.b64 %0, {%1, %1};" : "=l"(r) : "f"(x));
    return r;
}
__device__ __forceinline__ void unpack2(unsigned long long v, float& lo, float& hi) {
    asm("mov.b64 {%0, %1}, %2;" : "=f"(lo), "=f"(hi) : "l"(v));
}
__device__ __forceinline__ void ffma2(unsigned long long& d,
                                      unsigned long long a, unsigned long long b) {
    asm("fma.rn.f32x2 %0, %1, %2, %0;" : "+l"(d) : "l"(a), "l"(b));
}

__device__ __forceinline__ float sigmoidf_(float x) {
    float e = __expf(-x);                  // x<<0: e=inf -> 0 ; x>>0: e=0 -> 1
    return __fdividef(1.f, 1.f + e);
}
__device__ __forceinline__ float tanhf_(float x) {
    float ax = fabsf(x);
    float e  = __expf(-2.f * ax);          // e in (0,1], no overflow
    float r  = (1.f - e) * __fdividef(1.f, 1.f + e);
    return copysignf(r, x);
}

__global__ void __launch_bounds__(TPB, 1)
lstm_dec(const float* __restrict__ obs,    // [20][N][2]
         const float* __restrict__ h0,     // [N][192]
         const float* __restrict__ w_ih,   // [768][2]
         const float* __restrict__ w_hh,   // [768][192]
         const float* __restrict__ b_ih,   // [768]
         const float* __restrict__ b_hh,   // [768]
         const float* __restrict__ w_out,  // [2][192]
         const float* __restrict__ b_out,  // [2]
         float* __restrict__ out)          // [20][N][2]
{
    extern __shared__ float sm[];
    float* w_s    = sm;                     // 96 pair-rows x PSTR, (q,q+1) interleaved
    float* h_s    = w_s    + W_S_FLOATS;    // [64][192]
    float* x_s    = h_s    + H_S_FLOATS;    // [64][2]
    float* wih_s  = x_s    + ROWSB*2;       // [768][2]
    float* bias_s = wih_s  + G4*2;          // [768] = b_ih + b_hh
    float* wout_s = bias_s + G4;            // [2][192]
    float* bout_s = wout_s + 2*HID;         // [2]

    const int tid = threadIdx.x;
    const int tg  = tid & 15;               // gate group (16)
    const int tr  = tid >> 4;               // row group  (16), 4 rows each
    const size_t rowg = (size_t)blockIdx.x * ROWSB;

    // ---- one-time staging ----
    for (int i = tid; i < H_S_FLOATS/4; i += TPB)
        reinterpret_cast<float4*>(h_s)[i] =
            reinterpret_cast<const float4*>(h0 + rowg*HID)[i];
    for (int i = tid; i < G4; i += TPB) {
        bias_s[i]     = b_ih[i] + b_hh[i];
        wih_s[2*i+0]  = w_ih[2*i+0];
        wih_s[2*i+1]  = w_ih[2*i+1];
    }
    for (int i = tid; i < 2*HID; i += TPB) wout_s[i] = w_out[i];
    if (tid < 2) bout_s[tid] = b_out[tid];

    float c_reg[4][4][3];    // [row][chunk][j]
    float hn_reg[4][4][3];
#pragma unroll
    for (int r = 0; r < 4; r++)
#pragma unroll
        for (int ch = 0; ch < 4; ch++)
#pragma unroll
            for (int j = 0; j < 3; j++) c_reg[r][ch][j] = 0.f;

    int woff[2][3];
#pragma unroll
    for (int qp = 0; qp < 2; qp++)
#pragma unroll
        for (int j = 0; j < 3; j++)
            woff[qp][j] = (qp*48 + tg*3 + j) * PSTR;
    int hoff[4];
#pragma unroll
    for (int r = 0; r < 4; r++) hoff[r] = (tr*4 + r) * HID;

    for (int t = 0; t < TSTEPS; t++) {
        const int it = (t == 0) ? 0 : (t - 1);   // xs index: [0,0,1,...,18]

        for (int ch = 0; ch < 4; ch++) {
            __syncthreads();   // prior users of w_s / x_s are done
            // stage w chunk: global gate rows {q*192 + ch*48 + jj}, packed (q0,q1)/(q2,q3)
            for (int i = tid; i < 192*48; i += TPB) {
                const int lrow = i / 48;
                const int c4   = i - lrow*48;
                const int q    = lrow / 48;
                const int jj   = lrow - q*48;
                const float4 v = *reinterpret_cast<const float4*>(
                    w_hh + (size_t)(q*192 + ch*48 + jj)*HID + c4*4);
                float* dst = w_s + ((q >> 1)*48 + jj)*PSTR + c4*8 + (q & 1);
                dst[0] = v.x; dst[2] = v.y; dst[4] = v.z; dst[6] = v.w;
            }
            if (ch == 0 && tid < ROWSB*2)
                x_s[tid] = obs[((size_t)it*NBATCH + rowg)*2 + tid];
            __syncthreads();

            // acc init: x @ Wih^T + (b_ih + b_hh), packed (i,f) and (g,o)
            unsigned long long acc[2][3][4];
#pragma unroll
            for (int r = 0; r < 4; r++) {
                const float x0 = x_s[(tr*4 + r)*2 + 0];
                const float x1 = x_s[(tr*4 + r)*2 + 1];
#pragma unroll
                for (int qp = 0; qp < 2; qp++)
#pragma unroll
                    for (int j = 0; j < 3; j++) {
                        const int g0 = (2*qp)*192 + ch*48 + tg*3 + j;
                        const int g1 = g0 + 192;
                        const float a0 = fmaf(x0, wih_s[2*g0],
                                         fmaf(x1, wih_s[2*g0+1], bias_s[g0]));
                        const float a1 = fmaf(x0, wih_s[2*g1],
                                         fmaf(x1, wih_s[2*g1+1], bias_s[g1]));
                        acc[qp][j][r] = pack2(a0, a1);
                    }
            }

            // K sweep: acc += h_old[k] * w[gatepair][k]  (packed f32x2)
#pragma unroll 2
            for (int k = 0; k < HID; k += 4) {
                unsigned long long hsp[4][4];
#pragma unroll
                for (int r = 0; r < 4; r++) {
                    const float4 hv = *reinterpret_cast<const float4*>(h_s + hoff[r] + k);
                    hsp[r][0] = splat2(hv.x); hsp[r][1] = splat2(hv.y);
                    hsp[r][2] = splat2(hv.z); hsp[r][3] = splat2(hv.w);
                }
#pragma unroll
                for (int qp = 0; qp < 2; qp++)
#pragma unroll
                    for (int j = 0; j < 3; j++) {
                        const float* wp = w_s + woff[qp][j] + k*2;
                        const ulonglong2 wA = *reinterpret_cast<const ulonglong2*>(wp);
                        const ulonglong2 wB = *reinterpret_cast<const ulonglong2*>(wp + 4);
#pragma unroll
                        for (int r = 0; r < 4; r++) {
                            ffma2(acc[qp][j][r], hsp[r][0], wA.x);
                            ffma2(acc[qp][j][r], hsp[r][1], wA.y);
                            ffma2(acc[qp][j][r], hsp[r][2], wB.x);
                            ffma2(acc[qp][j][r], hsp[r][3], wB.y);
                        }
                    }
            }

            // activations + state update for this hidden chunk
#pragma unroll
            for (int r = 0; r < 4; r++)
#pragma unroll
                for (int j = 0; j < 3; j++) {
                    float iv, fv, gv, ov;
                    unpack2(acc[0][j][r], iv, fv);
                    unpack2(acc[1][j][r], gv, ov);
                    iv = sigmoidf_(iv); fv = sigmoidf_(fv);
                    gv = tanhf_(gv);    ov = sigmoidf_(ov);
                    const float cn = fmaf(fv, c_reg[r][ch][j], iv * gv);
                    c_reg[r][ch][j]  = cn;
                    hn_reg[r][ch][j] = ov * tanhf_(cn);
                }
        } // ch

        __syncthreads();   // all reads of h_old complete
#pragma unroll
        for (int r = 0; r < 4; r++)
#pragma unroll
            for (int ch = 0; ch < 4; ch++)
#pragma unroll
                for (int j = 0; j < 3; j++)
                    h_s[hoff[r] + ch*48 + tg*3 + j] = hn_reg[r][ch][j];
        __syncthreads();   // h_new visible

        // out[t] = h_new @ w_out^T + b_out
        if (tid < ROWSB*2) {
            const int r  = tid >> 1, cc = tid & 1;
            const float* hp = h_s + r*HID;
            const float* wp = wout_s + cc*HID;
            float s0 = 0.f, s1 = 0.f, s2 = 0.f, s3 = 0.f;
#pragma unroll
            for (int k = 0; k < HID; k += 4) {
                s0 = fmaf(hp[k+0], wp[k+0], s0);
                s1 = fmaf(hp[k+1], wp[k+1], s1);
                s2 = fmaf(hp[k+2], wp[k+2], s2);
                s3 = fmaf(hp[k+3], wp[k+3], s3);
            }
            out[((size_t)t*NBATCH + rowg + r)*2 + cc] = (s0+s1) + (s2+s3) + bout_s[cc];
        }
    }
}

extern "C" void kernel_launch(void* const* d_in, const int* in_sizes, int n_in,
                              void* d_out, int out_size)
{
    const float* obs   = (const float*)d_in[0];
    const float* h0    = (const float*)d_in[1];
    const float* w_ih  = (const float*)d_in[2];
    const float* w_hh  = (const float*)d_in[3];
    const float* b_ih  = (const float*)d_in[4];
    const float* b_hh  = (const float*)d_in[5];
    const float* w_out = (const float*)d_in[6];
    const float* b_out = (const float*)d_in[7];
    float* out = (float*)d_out;

    cudaFuncSetAttribute(lstm_dec, cudaFuncAttributeMaxDynamicSharedMemorySize,
                         SMEM_BYTES);
    lstm_dec<<<NBATCH / ROWSB, TPB, SMEM_BYTES>>>(obs, h0, w_ih, w_hh,
                                                  b_ih, b_hh, w_out, b_out, out);
}

// round 6
// speedup vs baseline: 1.1344x; 1.1344x over previous
#include <cuda_runtime.h>
#include <math.h>

#define TPB     256
#define ROWSB   64
#define HID     192
#define HSTR    196      // padded h row stride (floats), 16B-aligned, 2-way banks
#define TSTEPS  20
#define NBATCH  131072

// w_pack: [ch=6][k4=48][g=4][lane=32] float4  (float4 = w[g*192+ch*32+lane][4k4..4k4+3])
#define WPACK_F4   36864
#define CHUNK_F4   6144          // float4s per chunk (96 KB)

#define W_S_FLOATS   (CHUNK_F4*4)        // 24576
#define H_S_FLOATS   (ROWSB*HSTR)        // 12544
#define SMEM_FLOATS  (W_S_FLOATS + 2*H_S_FLOATS + 128 + 1536 + 768 + 384 + 2)
#define SMEM_BYTES   (SMEM_FLOATS * 4)

__device__ float4 g_wpack[WPACK_F4];

// ---- f32x2 helpers ----
__device__ __forceinline__ unsigned long long pack2(float lo, float hi) {
    unsigned long long r;
    asm("mov.b64 %0, {%1, %2};" : "=l"(r) : "f"(lo), "f"(hi));
    return r;
}
__device__ __forceinline__ void unpack2(unsigned long long v, float& lo, float& hi) {
    asm("mov.b64 {%0, %1}, %2;" : "=f"(lo), "=f"(hi) : "l"(v));
}
__device__ __forceinline__ void ffma2(unsigned long long& d,
                                      unsigned long long a, unsigned long long b) {
    asm("fma.rn.f32x2 %0, %1, %2, %0;" : "+l"(d) : "l"(a), "l"(b));
}

__device__ __forceinline__ float sigmoidf_(float x) {
    float e = __expf(-x);
    return __fdividef(1.f, 1.f + e);
}
__device__ __forceinline__ float tanhf_(float x) {
    float ax = fabsf(x);
    float e  = __expf(-2.f * ax);
    float r  = (1.f - e) * __fdividef(1.f, 1.f + e);
    return copysignf(r, x);
}

// ---- prepack w_hh [768][192] -> g_wpack tile layout ----
__global__ void prepack_w(const float* __restrict__ w_hh) {
    const int e = blockIdx.x * 256 + threadIdx.x;   // 144 blocks * 256 = 36864
    const int l  = e & 31;
    const int g  = (e >> 5) & 3;
    const int k4 = (e >> 7) % 48;
    const int ch = e / CHUNK_F4;
    const int grow = g * HID + ch * 32 + l;
    g_wpack[e] = *reinterpret_cast<const float4*>(w_hh + (size_t)grow * HID + k4 * 4);
}

__global__ void __launch_bounds__(TPB, 1)
lstm_dec(const float* __restrict__ obs,    // [20][N][2]
         const float* __restrict__ h0,     // [N][192]
         const float* __restrict__ w_ih,   // [768][2]
         const float* __restrict__ b_ih,   // [768]
         const float* __restrict__ b_hh,   // [768]
         const float* __restrict__ w_out,  // [2][192]
         const float* __restrict__ b_out,  // [2]
         float* __restrict__ out)          // [20][N][2]
{
    extern __shared__ float sm[];
    float* w_s    = sm;                       // 24576
    float* h_a    = w_s  + W_S_FLOATS;        // [64][HSTR]
    float* h_b    = h_a  + H_S_FLOATS;        // [64][HSTR]
    float* x_s    = h_b  + H_S_FLOATS;        // [64][2]
    float* wih_s  = x_s  + 128;               // [768][2]
    float* bias_s = wih_s + 1536;             // [768]
    float* wout_s = bias_s + 768;             // [2][192]
    float* bout_s = wout_s + 384;             // [2]

    const int tid  = threadIdx.x;
    const int lane = tid & 31;
    const int wrp  = tid >> 5;                 // 0..7 ; warp owns rows wrp*8..wrp*8+7
    const size_t rowg = (size_t)blockIdx.x * ROWSB;

    // one-time staging
    for (int i = tid; i < ROWSB * (HID/4); i += TPB) {
        const int r = i / (HID/4), c4 = i - r*(HID/4);
        *reinterpret_cast<float4*>(h_a + r*HSTR + c4*4) =
            reinterpret_cast<const float4*>(h0 + rowg*HID)[r*(HID/4) + c4];
    }
    for (int i = tid; i < 768; i += TPB) {
        bias_s[i]    = b_ih[i] + b_hh[i];
        wih_s[2*i+0] = w_ih[2*i+0];
        wih_s[2*i+1] = w_ih[2*i+1];
    }
    for (int i = tid; i < 2*HID; i += TPB) wout_s[i] = w_out[i];
    if (tid < 2) bout_s[tid] = b_out[tid];

    float c_reg[6][8];
#pragma unroll
    for (int ch = 0; ch < 6; ch++)
#pragma unroll
        for (int r = 0; r < 8; r++) c_reg[ch][r] = 0.f;

    for (int t = 0; t < TSTEPS; t++) {
        const float* hold = (t & 1) ? h_b : h_a;
        float*       hnew = (t & 1) ? h_a : h_b;
        const int it = (t == 0) ? 0 : (t - 1);

#pragma unroll
        for (int ch = 0; ch < 6; ch++) {
            __syncthreads();   // prior users of w_s / x_s done
            {
                const float4* src = g_wpack + ch * CHUNK_F4;
                float4* dst = reinterpret_cast<float4*>(w_s);
#pragma unroll
                for (int i = 0; i < CHUNK_F4 / TPB; i++)
                    dst[tid + i*TPB] = src[tid + i*TPB];
            }
            if (ch == 0 && tid < ROWSB*2)
                x_s[tid] = obs[((size_t)it*NBATCH + rowg)*2 + tid];
            __syncthreads();

            // acc init: x @ Wih^T + bias, even half only
            const int u = ch*32 + lane;
            float wih0[4], wih1[4], bb[4];
#pragma unroll
            for (int g = 0; g < 4; g++) {
                const int grow = g*HID + u;
                wih0[g] = wih_s[2*grow];
                wih1[g] = wih_s[2*grow+1];
                bb[g]   = bias_s[grow];
            }
            unsigned long long acc[4][8];
#pragma unroll
            for (int r = 0; r < 8; r++) {
                const float x0 = x_s[(wrp*8 + r)*2 + 0];
                const float x1 = x_s[(wrp*8 + r)*2 + 1];
#pragma unroll
                for (int g = 0; g < 4; g++)
                    acc[g][r] = pack2(fmaf(x0, wih0[g], fmaf(x1, wih1[g], bb[g])), 0.f);
            }

            // K sweep: k-packed f32x2, no splats
            const float* wp = w_s + lane*4;
            const float* hp = hold + wrp*8*HSTR;
#pragma unroll 1
            for (int k4 = 0; k4 < 48; k4++) {
                ulonglong2 wv[4];
#pragma unroll
                for (int g = 0; g < 4; g++)
                    wv[g] = *reinterpret_cast<const ulonglong2*>(wp + k4*512 + g*128);
#pragma unroll
                for (int r = 0; r < 8; r++) {
                    const ulonglong2 hv =
                        *reinterpret_cast<const ulonglong2*>(hp + r*HSTR + k4*4);
#pragma unroll
                    for (int g = 0; g < 4; g++) {
                        ffma2(acc[g][r], hv.x, wv[g].x);
                        ffma2(acc[g][r], hv.y, wv[g].y);
                    }
                }
            }

            // activations + state update (lane owns unit u, rows wrp*8..+7)
#pragma unroll
            for (int r = 0; r < 8; r++) {
                float lo, hi;
                unpack2(acc[0][r], lo, hi); const float iv = sigmoidf_(lo + hi);
                unpack2(acc[1][r], lo, hi); const float fv = sigmoidf_(lo + hi);
                unpack2(acc[2][r], lo, hi); const float gv = tanhf_(lo + hi);
                unpack2(acc[3][r], lo, hi); const float ov = sigmoidf_(lo + hi);
                const float cn = fmaf(fv, c_reg[ch][r], iv * gv);
                c_reg[ch][r] = cn;
                hnew[(wrp*8 + r)*HSTR + u] = ov * tanhf_(cn);
            }
        } // ch

        __syncthreads();   // hnew complete

        // out[t] = h_new @ w_out^T + b_out
        if (tid < ROWSB*2) {
            const int r = tid >> 1, cc = tid & 1;
            const float* hpn = hnew + r*HSTR;
            const float* wpn = wout_s + cc*HID;
            float s0 = 0.f, s1 = 0.f, s2 = 0.f, s3 = 0.f;
#pragma unroll
            for (int k = 0; k < HID; k += 4) {
                s0 = fmaf(hpn[k+0], wpn[k+0], s0);
                s1 = fmaf(hpn[k+1], wpn[k+1], s1);
                s2 = fmaf(hpn[k+2], wpn[k+2], s2);
                s3 = fmaf(hpn[k+3], wpn[k+3], s3);
            }
            out[((size_t)t*NBATCH + rowg + r)*2 + cc] = (s0+s1) + (s2+s3) + bout_s[cc];
        }
    }
}

extern "C" void kernel_launch(void* const* d_in, const int* in_sizes, int n_in,
                              void* d_out, int out_size)
{
    const float* obs   = (const float*)d_in[0];
    const float* h0    = (const float*)d_in[1];
    const float* w_ih  = (const float*)d_in[2];
    const float* w_hh  = (const float*)d_in[3];
    const float* b_ih  = (const float*)d_in[4];
    const float* b_hh  = (const float*)d_in[5];
    const float* w_out = (const float*)d_in[6];
    const float* b_out = (const float*)d_in[7];
    float* out = (float*)d_out;

    prepack_w<<<WPACK_F4 / 256, 256>>>(w_hh);

    cudaFuncSetAttribute(lstm_dec, cudaFuncAttributeMaxDynamicSharedMemorySize,
                         SMEM_BYTES);
    lstm_dec<<<NBATCH / ROWSB, TPB, SMEM_BYTES>>>(obs, h0, w_ih,
                                                  b_ih, b_hh, w_out, b_out, out);
}

// round 9
// speedup vs baseline: 2.3209x; 2.0460x over previous
#include <cuda_runtime.h>
#include <cuda_bf16.h>
#include <math.h>
#include <stdint.h>

#define TPB    256
#define MROWS  64
#define HID    192
#define TSTEPS 20
#define NBATCH 131072
#define NCH    24        // gate chunks of 32
#define KSTEPS 12
#define ASTR   400       // A/B row stride in bytes (200 bf16) -> conflict-free ldmatrix

// SMEM byte offsets
#define A_OFF    0       // [par=2][term=2][64 rows][ASTR]
#define APAR     51200
#define ATERM    25600
#define B_OFF    102400  // [stage=2][term=2][32 n][ASTR]
#define BSTAGE   25600
#define BTERM    12800
#define C_OFF    153600  // c: [64][CSTR] f32
#define CSTR     197
#define WIH_OFF  204032  // [768][2] f32
#define BIAS_OFF 210176  // [768] f32
#define WOUT_OFF 213248  // [2][192] f32
#define X_OFF    214784  // [64][2] f32
#define SMEM_BYTES 215296

// prepacked B: [24 chunks][2 terms][32 n][200 k] bf16 (term0=hi, term1=lo)
__device__ uint4 g_bpack[38400];   // 614400 B, 16B-aligned

// ---------------- helpers ----------------
__device__ __forceinline__ uint32_t smem_u32(const void* p) {
    uint32_t a;
    asm("{ .reg .u64 t; cvta.to.shared.u64 t, %1; cvt.u32.u64 %0, t; }"
        : "=r"(a) : "l"(p));
    return a;
}
__device__ __forceinline__ void ldmx4(uint32_t* r, uint32_t addr) {
    asm volatile("ldmatrix.sync.aligned.m8n8.x4.shared.b16 {%0,%1,%2,%3}, [%4];"
                 : "=r"(r[0]), "=r"(r[1]), "=r"(r[2]), "=r"(r[3]) : "r"(addr));
}
__device__ __forceinline__ void mma16816(float* c, const uint32_t* a,
                                         uint32_t b0, uint32_t b1) {
    asm volatile(
        "mma.sync.aligned.m16n8k16.row.col.f32.bf16.bf16.f32 "
        "{%0,%1,%2,%3}, {%4,%5,%6,%7}, {%8,%9}, {%0,%1,%2,%3};"
        : "+f"(c[0]), "+f"(c[1]), "+f"(c[2]), "+f"(c[3])
        : "r"(a[0]), "r"(a[1]), "r"(a[2]), "r"(a[3]), "r"(b0), "r"(b1));
}
__device__ __forceinline__ void cpasync16(uint32_t dst, const void* src) {
    asm volatile("cp.async.cg.shared.global [%0], [%1], 16;"
                 :: "r"(dst), "l"(src));
}
__device__ __forceinline__ float sigmoidf_(float x) {
    float e = __expf(-x);
    return __fdividef(1.f, 1.f + e);
}
__device__ __forceinline__ float tanhf_(float x) {
    float ax = fabsf(x);
    float e  = __expf(-2.f * ax);
    float r  = (1.f - e) * __fdividef(1.f, 1.f + e);
    return copysignf(r, x);
}

// ---------------- prepack: w_hh -> unit-paired hi/lo bf16 tiles ----------------
// Column n (0..31) of chunk cc: half=n>>4, n'=n&15, u_local=(n'&7)>>1,
// gate g=(n'&1)+2*(n'>>3), unit U=cc*8+half*4+u_local, grow=g*192+U.
// This makes MMA thread l own all 4 gates of unit (l&3) at cols {c,c+1,c+8,c+9}.
__global__ void prepack(const float* __restrict__ w_hh) {
    const int e   = blockIdx.x * 256 + threadIdx.x;    // 1200 blocks -> 307200
    const int k   = e % 200;
    const int n   = (e / 200) & 31;
    const int term = (e / 6400) & 1;
    const int cc  = e / 12800;
    const int np  = n & 15;
    const int U   = cc * 8 + (n >> 4) * 4 + ((np & 7) >> 1);
    const int g   = (np & 1) + 2 * (np >> 3);
    const int grow = g * HID + U;
    const float v = (k < HID) ? w_hh[(size_t)grow * HID + k] : 0.f;
    const __nv_bfloat16 hi = __float2bfloat16(v);
    ((__nv_bfloat16*)g_bpack)[e] =
        term ? __float2bfloat16(v - __bfloat162float(hi)) : hi;
}

// ---------------- main kernel ----------------
__global__ void __launch_bounds__(TPB, 1)
lstm_mma(const float* __restrict__ obs,    // [20][N][2]
         const float* __restrict__ h0,     // [N][192]
         const float* __restrict__ w_ih,   // [768][2]
         const float* __restrict__ b_ih,   // [768]
         const float* __restrict__ b_hh,   // [768]
         const float* __restrict__ w_out,  // [2][192]
         const float* __restrict__ b_out,  // [2]
         float* __restrict__ out)          // [20][N][2]
{
    extern __shared__ char sm[];
    const uint32_t smb = smem_u32(sm);
    float* c_s    = (float*)(sm + C_OFF);
    float* wih_s  = (float*)(sm + WIH_OFF);
    float* bias_s = (float*)(sm + BIAS_OFF);
    float* wout_s = (float*)(sm + WOUT_OFF);
    float* x_s    = (float*)(sm + X_OFF);

    const int tid  = threadIdx.x;
    const int lane = tid & 31;
    const int wid  = tid >> 5;
    const int mb   = (wid & 3) * 16;       // warp's 16-row base
    const int half = wid >> 2;             // gate-half within chunk
    const size_t rowg = (size_t)blockIdx.x * MROWS;

    // ---- one-time staging ----
    for (int i = tid; i < MROWS * HID; i += TPB) {       // h0 -> A[par=0] hi/lo
        const int r = i / HID, k = i - r * HID;
        const float v = h0[(rowg + r) * HID + k];
        const __nv_bfloat16 hi = __float2bfloat16(v);
        const __nv_bfloat16 lo = __float2bfloat16(v - __bfloat162float(hi));
        *(__nv_bfloat16*)(sm + A_OFF + r * ASTR + k * 2) = hi;
        *(__nv_bfloat16*)(sm + A_OFF + ATERM + r * ASTR + k * 2) = lo;
    }
    for (int i = tid; i < MROWS * CSTR; i += TPB) c_s[i] = 0.f;
    for (int i = tid; i < 768; i += TPB) {
        wih_s[2 * i]     = w_ih[2 * i];
        wih_s[2 * i + 1] = w_ih[2 * i + 1];
        bias_s[i]        = b_ih[i] + b_hh[i];
    }
    for (int i = tid; i < 384; i += TPB) wout_s[i] = w_out[i];
    if (tid < 128) x_s[tid] = obs[rowg * 2 + tid];       // t=0 uses obs[0]
    const float boutv = (tid < 128) ? b_out[tid & 1] : 0.f;

    // prefetch chunk 0 -> stage 0
    {
        const uint4* src = g_bpack;
        const uint32_t dst = smb + B_OFF;
        for (int i = tid; i < 1600; i += TPB) cpasync16(dst + i * 16, src + i);
        asm volatile("cp.async.commit_group;" ::: "memory");
    }

    // per-lane ldmatrix offsets (bytes)
    const uint32_t a_lane_off =
        (uint32_t)((mb + (lane & 7) + ((lane >> 3) & 1) * 8) * ASTR
                   + ((lane >> 4) & 1) * 16);
    const uint32_t b_lane_off =
        (uint32_t)((half * 16 + ((lane >> 4) & 1) * 8 + (lane & 7)) * ASTR
                   + ((lane >> 3) & 1) * 16);
    const int ulan = lane & 3;             // unit-within-4 this thread owns
    const int r0   = mb + (lane >> 2);     // first owned row (second = r0+8)

    for (int t = 0; t < TSTEPS; t++) {
        const int par = t & 1;
        const uint32_t a_hi = smb + A_OFF + par * APAR + a_lane_off;
        const uint32_t a_lo = a_hi + ATERM;
        char* an_hi = sm + A_OFF + (par ^ 1) * APAR;   // h_new destination
        char* an_lo = an_hi + ATERM;

#pragma unroll 1
        for (int cc = 0; cc < NCH; cc++) {
            asm volatile("cp.async.wait_group 0;" ::: "memory");
            __syncthreads();   // stage (cc&1) ready; all reads of other stage done

            // prefetch next chunk into the other stage
            {
                const int nc = (cc + 1 == NCH) ? 0 : cc + 1;
                const uint4* src = g_bpack + nc * 1600;
                const uint32_t dst = smb + B_OFF + ((cc + 1) & 1) * BSTAGE;
                for (int i = tid; i < 1600; i += TPB) cpasync16(dst + i * 16, src + i);
                asm volatile("cp.async.commit_group;" ::: "memory");
            }

            // accumulator init: bias + x @ w_ih^T (gate order i,f in d0; g,o in d1)
            const int U = cc * 8 + half * 4 + ulan;
            float d0[4], d1[4];
            {
                const float x00 = x_s[r0 * 2],       x01 = x_s[r0 * 2 + 1];
                const float x10 = x_s[(r0 + 8) * 2], x11 = x_s[(r0 + 8) * 2 + 1];
#pragma unroll
                for (int g = 0; g < 2; g++) {
                    const int grow = g * HID + U;
                    const float w0 = wih_s[2 * grow], w1 = wih_s[2 * grow + 1];
                    const float bb = bias_s[grow];
                    d0[g]     = fmaf(x00, w0, fmaf(x01, w1, bb));
                    d0[g + 2] = fmaf(x10, w0, fmaf(x11, w1, bb));
                }
#pragma unroll
                for (int g = 0; g < 2; g++) {
                    const int grow = (g + 2) * HID + U;
                    const float w0 = wih_s[2 * grow], w1 = wih_s[2 * grow + 1];
                    const float bb = bias_s[grow];
                    d1[g]     = fmaf(x00, w0, fmaf(x01, w1, bb));
                    d1[g + 2] = fmaf(x10, w0, fmaf(x11, w1, bb));
                }
            }

            // K sweep: 12 k-steps x (A_hi*B_hi + A_hi*B_lo + A_lo*B_hi)
            const uint32_t bb0 = smb + B_OFF + (cc & 1) * BSTAGE + b_lane_off;
#pragma unroll
            for (int ks = 0; ks < KSTEPS; ks++) {
                uint32_t ah[4], al[4], bh[4], bl[4];
                ldmx4(ah, a_hi + ks * 32);
                ldmx4(bh, bb0 + ks * 32);
                ldmx4(al, a_lo + ks * 32);
                ldmx4(bl, bb0 + BTERM + ks * 32);
                mma16816(d0, ah, bh[0], bh[1]);
                mma16816(d1, ah, bh[2], bh[3]);
                mma16816(d0, ah, bl[0], bl[1]);
                mma16816(d1, ah, bl[2], bl[3]);
                mma16816(d0, al, bh[0], bh[1]);
                mma16816(d1, al, bh[2], bh[3]);
            }

            // epilogue: this thread owns unit U at rows r0 and r0+8
#pragma unroll
            for (int rr = 0; rr < 2; rr++) {
                const int r = r0 + rr * 8;
                const float iv = sigmoidf_(d0[rr * 2 + 0]);
                const float fv = sigmoidf_(d0[rr * 2 + 1]);
                const float gv = tanhf_(d1[rr * 2 + 0]);
                const float ov = sigmoidf_(d1[rr * 2 + 1]);
                const float cn = fmaf(fv, c_s[r * CSTR + U], iv * gv);
                c_s[r * CSTR + U] = cn;
                const float hv = ov * tanhf_(cn);
                const __nv_bfloat16 hhi = __float2bfloat16(hv);
                const __nv_bfloat16 hlo =
                    __float2bfloat16(hv - __bfloat162float(hhi));
                *(__nv_bfloat16*)(an_hi + r * ASTR + U * 2) = hhi;
                *(__nv_bfloat16*)(an_lo + r * ASTR + U * 2) = hlo;
            }
        } // cc

        __syncthreads();   // h_new (A[par^1]) complete

        if (tid < 128) {
            // out[t] = h_t @ w_out^T + b_out  (h = hi + lo for fp32-grade accuracy)
            const int r = tid >> 1, comp = tid & 1;
            const __nv_bfloat162* ph = (const __nv_bfloat162*)(an_hi + r * ASTR);
            const __nv_bfloat162* pl = (const __nv_bfloat162*)(an_lo + r * ASTR);
            const float* wp = wout_s + comp * HID;
            float s0 = 0.f, s1 = 0.f;
#pragma unroll 4
            for (int u2 = 0; u2 < 96; u2++) {
                const float2 hh = __bfloat1622float2(ph[u2]);
                const float2 ll = __bfloat1622float2(pl[u2]);
                s0 = fmaf(hh.x + ll.x, wp[2 * u2],     s0);
                s1 = fmaf(hh.y + ll.y, wp[2 * u2 + 1], s1);
            }
            out[((size_t)t * NBATCH + rowg + r) * 2 + comp] = s0 + s1 + boutv;
        } else {
            // stage x for step t+1 (xs index = t); extra load at t=19 is harmless
            x_s[tid - 128] = obs[((size_t)t * NBATCH + rowg) * 2 + (tid - 128)];
        }
        // visibility of x_s / reuse of buffers is covered by the barrier at the
        // top of the next step's chunk 0
    } // t
}

extern "C" void kernel_launch(void* const* d_in, const int* in_sizes, int n_in,
                              void* d_out, int out_size)
{
    const float* obs   = (const float*)d_in[0];
    const float* h0    = (const float*)d_in[1];
    const float* w_ih  = (const float*)d_in[2];
    const float* w_hh  = (const float*)d_in[3];
    const float* b_ih  = (const float*)d_in[4];
    const float* b_hh  = (const float*)d_in[5];
    const float* w_out = (const float*)d_in[6];
    const float* b_out = (const float*)d_in[7];
    float* out = (float*)d_out;

    prepack<<<1200, 256>>>(w_hh);

    cudaFuncSetAttribute(lstm_mma, cudaFuncAttributeMaxDynamicSharedMemorySize,
                         SMEM_BYTES);
    lstm_mma<<<NBATCH / MROWS, TPB, SMEM_BYTES>>>(obs, h0, w_ih, b_ih, b_hh,
                                                  w_out, b_out, out);
}

// round 11
// speedup vs baseline: 2.5360x; 1.0927x over previous
#include <cuda_runtime.h>
#include <cuda_bf16.h>
#include <math.h>
#include <stdint.h>

#define TPB    256
#define MROWS  64
#define HID    192
#define TSTEPS 20
#define NBATCH 131072
#define NCH    24        // gate chunks of 32
#define KSTEPS 12
#define ASTR   400       // A/B row stride in bytes (200 bf16) -> conflict-free ldmatrix
#define CSTR   201       // c row stride in floats -> conflict-free quad access

// SMEM byte offsets
#define A_OFF    0       // [par=2][term=2][64 rows][ASTR]
#define APAR     51200
#define ATERM    25600
#define B_OFF    102400  // [stage=2][term=2][32 n][ASTR]
#define BSTAGE   25600
#define BTERM    12800
#define C_OFF    153600  // c: [64][CSTR] f32 = 51456 B
#define WIH_OFF  205056  // [768][2] f32
#define BIAS_OFF 211200  // [768] f32
#define WOUT_OFF 214272  // [2][192] f32
#define X_OFF    215808  // [64][2] f32
#define SMEM_BYTES 216320

// prepacked B: [24 chunks][2 terms][32 n][200 k] bf16 (term0=hi, term1=lo)
__device__ uint4 g_bpack[38400];   // 614400 B

// ---------------- helpers ----------------
__device__ __forceinline__ uint32_t smem_u32(const void* p) {
    uint32_t a;
    asm("{ .reg .u64 t; cvta.to.shared.u64 t, %1; cvt.u32.u64 %0, t; }"
        : "=r"(a) : "l"(p));
    return a;
}
__device__ __forceinline__ void ldmx4(uint32_t* r, uint32_t addr) {
    asm volatile("ldmatrix.sync.aligned.m8n8.x4.shared.b16 {%0,%1,%2,%3}, [%4];"
                 : "=r"(r[0]), "=r"(r[1]), "=r"(r[2]), "=r"(r[3]) : "r"(addr));
}
__device__ __forceinline__ void mma16816(float* c, const uint32_t* a,
                                         uint32_t b0, uint32_t b1) {
    asm volatile(
        "mma.sync.aligned.m16n8k16.row.col.f32.bf16.bf16.f32 "
        "{%0,%1,%2,%3}, {%4,%5,%6,%7}, {%8,%9}, {%0,%1,%2,%3};"
        : "+f"(c[0]), "+f"(c[1]), "+f"(c[2]), "+f"(c[3])
        : "r"(a[0]), "r"(a[1]), "r"(a[2]), "r"(a[3]), "r"(b0), "r"(b1));
}
__device__ __forceinline__ void cpasync16(uint32_t dst, const void* src) {
    asm volatile("cp.async.cg.shared.global [%0], [%1], 16;"
                 :: "r"(dst), "l"(src));
}
__device__ __forceinline__ float sigmoidf_(float x) {
    float e = __expf(-x);
    return __fdividef(1.f, 1.f + e);
}
__device__ __forceinline__ float tanhf_(float x) {
    float ax = fabsf(x);
    float e  = __expf(-2.f * ax);
    float r  = (1.f - e) * __fdividef(1.f, 1.f + e);
    return copysignf(r, x);
}

// ---------------- prepack: w_hh -> unit-paired hi/lo bf16 tiles ----------------
// Column n (0..31) of chunk cc: U = cc*8 + (n>>4)*4 + ((n&7)>>1),
// g = (n&1) + 2*((n>>3)&1), grow = g*192 + U.
__global__ void prepack(const float* __restrict__ w_hh) {
    const int e   = blockIdx.x * 256 + threadIdx.x;    // 1200 blocks -> 307200
    const int k   = e % 200;
    const int n   = (e / 200) & 31;
    const int cc  = e / 12800;
    const int np  = n & 15;
    const int U   = cc * 8 + (n >> 4) * 4 + ((np & 7) >> 1);
    const int g   = (np & 1) + 2 * (np >> 3);
    const int grow = g * HID + U;
    const float v = (k < HID) ? w_hh[(size_t)grow * HID + k] : 0.f;
    const __nv_bfloat16 hi = __float2bfloat16(v);
    const int term = (e / 6400) & 1;
    ((__nv_bfloat16*)g_bpack)[e] =
        term ? __float2bfloat16(v - __bfloat162float(hi)) : hi;
}

// ---------------- main kernel ----------------
__global__ void __launch_bounds__(TPB, 1)
lstm_mma(const float* __restrict__ obs,    // [20][N][2]
         const float* __restrict__ h0,     // [N][192]
         const float* __restrict__ w_ih,   // [768][2]
         const float* __restrict__ b_ih,   // [768]
         const float* __restrict__ b_hh,   // [768]
         const float* __restrict__ w_out,  // [2][192]
         const float* __restrict__ b_out,  // [2]
         float* __restrict__ out)          // [20][N][2]
{
    extern __shared__ char sm[];
    const uint32_t smb = smem_u32(sm);
    float* c_s    = (float*)(sm + C_OFF);
    float* wih_s  = (float*)(sm + WIH_OFF);
    float* bias_s = (float*)(sm + BIAS_OFF);
    float* wout_s = (float*)(sm + WOUT_OFF);
    float* x_s    = (float*)(sm + X_OFF);

    const int tid  = threadIdx.x;
    const int lane = tid & 31;
    const int wid  = tid >> 5;
    const int rg   = wid & 3;              // rowgroup: rows rg*16..+15
    const int cg   = wid >> 2;             // colgroup within 32-col chunk
    const size_t rowg = (size_t)blockIdx.x * MROWS;

    // ---- one-time staging ----
    for (int i = tid; i < MROWS * HID; i += TPB) {       // h0 -> A[par=0] hi/lo
        const int r = i / HID, k = i - r * HID;
        const float v = h0[(rowg + r) * HID + k];
        const __nv_bfloat16 hi = __float2bfloat16(v);
        const __nv_bfloat16 lo = __float2bfloat16(v - __bfloat162float(hi));
        *(__nv_bfloat16*)(sm + A_OFF + r * ASTR + k * 2) = hi;
        *(__nv_bfloat16*)(sm + A_OFF + ATERM + r * ASTR + k * 2) = lo;
    }
    for (int i = tid; i < MROWS * CSTR; i += TPB) c_s[i] = 0.f;
    for (int i = tid; i < 768; i += TPB) {
        wih_s[2 * i]     = w_ih[2 * i];
        wih_s[2 * i + 1] = w_ih[2 * i + 1];
        bias_s[i]        = b_ih[i] + b_hh[i];
    }
    for (int i = tid; i < 384; i += TPB) wout_s[i] = w_out[i];
    if (tid < 128) x_s[tid] = obs[rowg * 2 + tid];       // t=0 uses obs[0]
    const float boutv = (tid < 128) ? b_out[tid & 1] : 0.f;

    // prefetch chunk 0 -> stage 0
    {
        const uint4* src = g_bpack;
        const uint32_t dst = smb + B_OFF;
        for (int i = tid; i < 1600; i += TPB) cpasync16(dst + i * 16, src + i);
        asm volatile("cp.async.commit_group;" ::: "memory");
    }

    // RACE FIX (round-10 bug): the step-0 A-fragment ldmatrix below reads h0
    // staged by OTHER threads. Must order the cooperative staging before any
    // A reads.
    __syncthreads();

    // per-lane ldmatrix offsets (bytes)
    const uint32_t a_lane_off =
        (uint32_t)((rg * 16 + (lane & 7) + ((lane >> 3) & 1) * 8) * ASTR
                   + ((lane >> 4) & 1) * 16);
    const uint32_t b_lane_off =
        (uint32_t)((cg * 16 + ((lane >> 4) & 1) * 8 + (lane & 7)) * ASTR
                   + ((lane >> 3) & 1) * 16);
    const int ulan = lane & 3;             // unit-within-4 this thread owns
    const int r0   = rg * 16 + (lane >> 2);

    const float* wout0 = wout_s + (tid & 1) * HID;   // for out-projection
    const int opr = tid >> 1;                        // out-projection row

    for (int t = 0; t < TSTEPS; t++) {
        const int par = t & 1;

        // ---- load persistent A fragments for this step (hi + lo, full K) ----
        // Safe: A[par] writes (h0 staging at t=0, epilogues at t>=1) are all
        // ordered before this point by the barrier above / end-of-step barrier.
        const uint32_t a_hi = smb + A_OFF + par * APAR + a_lane_off;
        uint32_t afh[KSTEPS][4], afl[KSTEPS][4];
#pragma unroll
        for (int ks = 0; ks < KSTEPS; ks++) {
            ldmx4(afh[ks], a_hi + ks * 32);
            ldmx4(afl[ks], a_hi + ATERM + ks * 32);
        }

        char* an_hi = sm + A_OFF + (par ^ 1) * APAR;   // h_new destination
        char* an_lo = an_hi + ATERM;

#pragma unroll 1
        for (int cc = 0; cc < NCH; cc++) {
            asm volatile("cp.async.wait_group 0;" ::: "memory");
            __syncthreads();   // stage (cc&1) ready; x_s visible (chunk 0)

            // prefetch next chunk into the other stage
            {
                const int nc = (cc + 1 == NCH) ? 0 : cc + 1;
                const uint4* src = g_bpack + nc * 1600;
                const uint32_t dst = smb + B_OFF + ((cc + 1) & 1) * BSTAGE;
                for (int i = tid; i < 1600; i += TPB) cpasync16(dst + i * 16, src + i);
                asm volatile("cp.async.commit_group;" ::: "memory");
            }

            // accumulator init: dA = bias + x@w_ih^T (chain A), dB = 0 (chain B)
            const int U = cc * 8 + cg * 4 + ulan;
            float dA0[4], dA1[4], dB0[4], dB1[4];
            {
                const float x00 = x_s[r0 * 2],       x01 = x_s[r0 * 2 + 1];
                const float x10 = x_s[(r0 + 8) * 2], x11 = x_s[(r0 + 8) * 2 + 1];
#pragma unroll
                for (int g = 0; g < 2; g++) {
                    const int grow = g * HID + U;
                    const float w0 = wih_s[2 * grow], w1 = wih_s[2 * grow + 1];
                    const float bb = bias_s[grow];
                    dA0[g]     = fmaf(x00, w0, fmaf(x01, w1, bb));
                    dA0[g + 2] = fmaf(x10, w0, fmaf(x11, w1, bb));
                }
#pragma unroll
                for (int g = 0; g < 2; g++) {
                    const int grow = (g + 2) * HID + U;
                    const float w0 = wih_s[2 * grow], w1 = wih_s[2 * grow + 1];
                    const float bb = bias_s[grow];
                    dA1[g]     = fmaf(x00, w0, fmaf(x01, w1, bb));
                    dA1[g + 2] = fmaf(x10, w0, fmaf(x11, w1, bb));
                }
#pragma unroll
                for (int j = 0; j < 4; j++) { dB0[j] = 0.f; dB1[j] = 0.f; }
            }

            // K sweep: B-only loads; A fragments already in registers
            const uint32_t bb0 = smb + B_OFF + (cc & 1) * BSTAGE + b_lane_off;
#pragma unroll
            for (int ks = 0; ks < KSTEPS; ks++) {
                uint32_t bh[4], bl[4];
                ldmx4(bh, bb0 + ks * 32);
                ldmx4(bl, bb0 + BTERM + ks * 32);
                mma16816(dA0, afh[ks], bh[0], bh[1]);   // chain A, cols 0-7
                mma16816(dA1, afh[ks], bh[2], bh[3]);   // chain A, cols 8-15
                mma16816(dB0, afh[ks], bl[0], bl[1]);   // chain B
                mma16816(dB1, afh[ks], bl[2], bl[3]);
                mma16816(dA0, afl[ks], bh[0], bh[1]);
                mma16816(dA1, afl[ks], bh[2], bh[3]);
            }

            // epilogue: thread owns unit U at rows r0 and r0+8
#pragma unroll
            for (int rr = 0; rr < 2; rr++) {
                const int r = r0 + rr * 8;
                const float iv = sigmoidf_(dA0[rr * 2 + 0] + dB0[rr * 2 + 0]);
                const float fv = sigmoidf_(dA0[rr * 2 + 1] + dB0[rr * 2 + 1]);
                const float gv = tanhf_(dA1[rr * 2 + 0] + dB1[rr * 2 + 0]);
                const float ov = sigmoidf_(dA1[rr * 2 + 1] + dB1[rr * 2 + 1]);
                const float cn = fmaf(fv, c_s[r * CSTR + U], iv * gv);
                c_s[r * CSTR + U] = cn;
                const float hv = ov * tanhf_(cn);
                const __nv_bfloat16 hhi = __float2bfloat16(hv);
                const __nv_bfloat16 hlo =
                    __float2bfloat16(hv - __bfloat162float(hhi));
                *(__nv_bfloat16*)(an_hi + r * ASTR + U * 2) = hhi;
                *(__nv_bfloat16*)(an_lo + r * ASTR + U * 2) = hlo;
            }
        } // cc

        __syncthreads();   // h_new (A[par^1]) complete

        if (tid < 128) {
            // out[t] = h_t @ w_out^T + b_out  (h = hi + lo for fp32-grade accuracy)
            const __nv_bfloat162* ph = (const __nv_bfloat162*)(an_hi + opr * ASTR);
            const __nv_bfloat162* pl = (const __nv_bfloat162*)(an_lo + opr * ASTR);
            float s0 = 0.f, s1 = 0.f;
#pragma unroll 4
            for (int u2 = 0; u2 < 96; u2++) {
                const float2 hh = __bfloat1622float2(ph[u2]);
                const float2 ll = __bfloat1622float2(pl[u2]);
                s0 = fmaf(hh.x + ll.x, wout0[2 * u2],     s0);
                s1 = fmaf(hh.y + ll.y, wout0[2 * u2 + 1], s1);
            }
            out[((size_t)t * NBATCH + rowg + opr) * 2 + (tid & 1)] = s0 + s1 + boutv;
        } else {
            // stage x for step t+1 (xs index = t); extra load at t=19 is harmless
            x_s[tid - 128] = obs[((size_t)t * NBATCH + rowg) * 2 + (tid - 128)];
        }
        // x_s visibility for next step covered by chunk-0 top barrier;
        // next step's A-fragment reads target A[par], written before the
        // end-of-step barrier above.
    } // t
}

extern "C" void kernel_launch(void* const* d_in, const int* in_sizes, int n_in,
                              void* d_out, int out_size)
{
    const float* obs   = (const float*)d_in[0];
    const float* h0    = (const float*)d_in[1];
    const float* w_ih  = (const float*)d_in[2];
    const float* w_hh  = (const float*)d_in[3];
    const float* b_ih  = (const float*)d_in[4];
    const float* b_hh  = (const float*)d_in[5];
    const float* w_out = (const float*)d_in[6];
    const float* b_out = (const float*)d_in[7];
    float* out = (float*)d_out;

    prepack<<<1200, 256>>>(w_hh);

    cudaFuncSetAttribute(lstm_mma, cudaFuncAttributeMaxDynamicSharedMemorySize,
                         SMEM_BYTES);
    lstm_mma<<<NBATCH / MROWS, TPB, SMEM_BYTES>>>(obs, h0, w_ih, b_ih, b_hh,
                                                  w_out, b_out, out);
}